// round 5
// baseline (speedup 1.0000x reference)
#include <cuda_runtime.h>

#define BB 2
#define SS 5
#define CC 256
#define HH 192
#define WW 192
#define KK 7
#define NH 28
#define NW 28
#define HID 16
#define STRIPS (BB * NH)          // 56
#define NCG (CC / 2)              // 128 channel-group blocks per strip
#define TPB 480
#define STRIP_G (SS * CC * NW)    // 35840 floats of means per strip

// Scratch (no cudaMalloc allowed)
__device__ float g_buf[BB * NH * SS * CC * NW];   // window means, [b,nh][s,c,nw]
__device__ float logits_buf[STRIPS * SS * NW];
__device__ int   sync_buf[2 * STRIPS];            // [0..55] counters, [56..111] flags

// ---------------------------------------------------------------------------
// Single fused kernel. Block = 2 channels of one strip (b, nh):
//   1. load 2ch x 5 slices x 7 rows tile into smem (7 front-batched float4/thr)
//   2. compute 7x7 window means from smem, store to g_buf, arrive on counter
//   3. leader (cg==0) spins for 128 arrivals, runs the tiny MLP -> logits,
//      publishes flag; siblings spin on flag (tile stays resident in smem)
//   4. softmax over S, weighted fuse from smem, interleaved coalesced store
// x is read from DRAM exactly ONCE.
// Deadlock-safe: 128 blocks/strip <= 148 min-resident blocks; bids contiguous
// per strip (blockIdx.x fastest) so the oldest strip is always fully resident.
// ---------------------------------------------------------------------------
__global__ __launch_bounds__(TPB) void k_fused(
    const float* __restrict__ x,
    const float* __restrict__ w1, const float* __restrict__ b1,
    const float* __restrict__ w2, const float* __restrict__ b2,
    const float* __restrict__ stat,
    float* __restrict__ out)
{
    const int cg = blockIdx.x;           // 0..127
    const int nh = blockIdx.y;
    const int b  = blockIdx.z;
    const int c0 = cg * 2;
    const int strip = b * NH + nh;
    const int t = threadIdx.x;

    extern __shared__ float smem[];
    float* sm   = smem;                  // [70][192] tile, row r=(ci*SS+s)*KK+kh
    float* slog = smem + 70 * WW;        // [140] logits [s][nw]
    float* sbig = slog + 140;            // [560] leader partials / softmax wts

    // ---- 1. load tile: 7 front-batched independent float4 loads per thread
    const int h0 = nh * KK;
    const float4* x4 = (const float4*)x;
    const int q  = t % 48;
    const int r0 = t / 48;               // 0..9
    float4 v[7];
    int rr[7];
    #pragma unroll
    for (int it = 0; it < 7; it++) {
        const int r  = r0 + it * 10;     // 0..69
        const int kh = r % KK;
        const int sc = r / KK;
        const int s  = sc % SS;
        const int ci = sc / SS;
        const int h  = h0 + kh;
        rr[it] = r;
        if (h < HH)
            v[it] = x4[((size_t)((b * SS + s) * CC + c0 + ci) * HH + h) * 48 + q];
        else
            v[it] = make_float4(0.f, 0.f, 0.f, 0.f);
    }
    #pragma unroll
    for (int it = 0; it < 7; it++)
        *(float4*)&sm[rr[it] * WW + q * 4] = v[it];
    __syncthreads();

    // ---- 2. window means for this block's 2 channels (280 tasks)
    if (t < 280) {
        const int ci = t / 140, rem = t % 140, s = rem / 28, nw = rem % 28;
        const float* rows = &sm[(ci * SS + s) * KK * WW];
        float sum = 0.f;
        #pragma unroll
        for (int kh = 0; kh < KK; kh++) {
            const float* rw = rows + kh * WW;
            #pragma unroll
            for (int i = 0; i < KK; i++) {
                const int w = nw * KK + i;
                if (w < WW) sum += rw[w];   // padded cols 192..195 are zero
            }
        }
        g_buf[(size_t)strip * STRIP_G + (s * CC + c0 + ci) * NW + nw]
            = sum * (1.0f / (KK * KK));
        __threadfence();
    }
    __syncthreads();
    if (t == 0) atomicAdd(&sync_buf[strip], 1);

    // ---- 3. logits: leader computes, siblings wait
    if (cg == 0) {
        if (t == 0)
            while (*(volatile int*)&sync_buf[strip] < NCG) __nanosleep(128);
        __syncthreads();
        __threadfence();
        const float* gs = g_buf + (size_t)strip * STRIP_G;
        // 560 tasks = (s, nw, j-group of 4); each: 256-c dot for 4 hidden units
        for (int task = t; task < 560; task += TPB) {
            const int s  = task / 112;
            const int rm = task % 112;
            const int nw = rm / 4;
            const int j0 = (rm % 4) * 4;
            float ha = b1[j0], hb = b1[j0 + 1], hc = b1[j0 + 2], hd = b1[j0 + 3];
            const float* gsc = gs + s * CC * NW + nw;
            #pragma unroll 4
            for (int c = 0; c < CC; c++) {
                const float gv = gsc[c * NW];
                ha = fmaf(gv, w1[(j0 + 0) * CC + c], ha);
                hb = fmaf(gv, w1[(j0 + 1) * CC + c], hb);
                hc = fmaf(gv, w1[(j0 + 2) * CC + c], hc);
                hd = fmaf(gv, w1[(j0 + 3) * CC + c], hd);
            }
            sbig[task] = fmaxf(ha, 0.f) * w2[j0]     + fmaxf(hb, 0.f) * w2[j0 + 1]
                       + fmaxf(hc, 0.f) * w2[j0 + 2] + fmaxf(hd, 0.f) * w2[j0 + 3];
        }
        __syncthreads();
        if (t < 140) {
            const int s = t / 28;
            const float lg = sbig[t * 4] + sbig[t * 4 + 1] + sbig[t * 4 + 2]
                           + sbig[t * 4 + 3] + b2[0] + stat[s];
            slog[t] = lg;
            logits_buf[strip * 140 + t] = lg;
            __threadfence();
        }
        __syncthreads();
        if (t == 0) atomicExch(&sync_buf[STRIPS + strip], 1);
    } else {
        if (t == 0)
            while (*(volatile int*)&sync_buf[STRIPS + strip] == 0) __nanosleep(128);
        __syncthreads();
        __threadfence();
        if (t < 140) slog[t] = logits_buf[strip * 140 + t];
        __syncthreads();
    }

    // ---- 4a. softmax over S (28 windows)
    if (t < NW) {
        float lg[SS];
        float mx = -1e30f;
        #pragma unroll
        for (int s = 0; s < SS; s++) { lg[s] = slog[s * NW + t]; mx = fmaxf(mx, lg[s]); }
        float sum = 0.f;
        #pragma unroll
        for (int s = 0; s < SS; s++) { lg[s] = expf(lg[s] - mx); sum += lg[s]; }
        const float inv = 1.f / sum;
        #pragma unroll
        for (int s = 0; s < SS; s++) sbig[s * NW + t] = lg[s] * inv;
    }
    __syncthreads();

    // ---- 4b. fuse + interleaved coalesced store
    if (t < 2 * WW) {
        const int ci   = t / WW;
        const int col  = t % WW;
        const int kw   = col / NW;
        const int nw   = col % NW;
        const int wsrc = nw * KK + kw;
        const bool valid = (wsrc < WW);

        float wts[SS];
        #pragma unroll
        for (int s = 0; s < SS; s++) wts[s] = sbig[s * NW + nw];

        const float* smc = sm + ci * SS * KK * WW;
        float* obase = out + (size_t)(b * CC + c0 + ci) * HH * WW;
        #pragma unroll
        for (int kh = 0; kh < KK; kh++) {
            const int y = kh * NH + nh;
            if (y < HH) {
                float vv = 0.f;
                if (valid) {
                    #pragma unroll
                    for (int s = 0; s < SS; s++)
                        vv = fmaf(wts[s], smc[(s * KK + kh) * WW + wsrc], vv);
                }
                obase[(size_t)y * WW + col] = vv;
            }
        }
    }
}

// ---------------------------------------------------------------------------
extern "C" void kernel_launch(void* const* d_in, const int* in_sizes, int n_in,
                              void* d_out, int out_size) {
    const float* x    = (const float*)d_in[0];
    const float* w1   = (const float*)d_in[1];
    const float* b1   = (const float*)d_in[2];
    const float* w2   = (const float*)d_in[3];
    const float* b2   = (const float*)d_in[4];
    const float* stat = (const float*)d_in[5];
    float* out = (float*)d_out;

    // reset counters/flags every call (graph-capturable memset node)
    void* sync_ptr = nullptr;
    cudaGetSymbolAddress(&sync_ptr, sync_buf);
    cudaMemsetAsync(sync_ptr, 0, sizeof(int) * 2 * STRIPS);

    const int smem_bytes = (70 * WW + 140 + 560) * sizeof(float);  // 56560 B
    cudaFuncSetAttribute(k_fused, cudaFuncAttributeMaxDynamicSharedMemorySize, smem_bytes);

    k_fused<<<dim3(NCG, NH, BB), TPB, smem_bytes>>>(x, w1, b1, w2, b2, stat, out);
}

// round 6
// speedup vs baseline: 7.8471x; 7.8471x over previous
#include <cuda_runtime.h>

#define BB 2
#define SS 5
#define CC 256
#define HH 192
#define WW 192
#define KK 7
#define NH 28
#define NW 28
#define HID 16

__device__ float g_buf[BB * SS * CC * NH * NW];       // 8.03 MB
__device__ float logits_buf[BB * SS * NH * NW];       // 31.4 KB

// ---------------------------------------------------------------------------
// Kernel 1: 7x7 window means. Block = 336 threads handles 7 independent
// strips of one (bs,c) image: 7 front-batched float4 loads per thread,
// one barrier, phase A uses all 336 threads (7 strips x 48 quads).
// grid (CC, BB*SS, 4), smem 43 KB -> 5 blocks/SM, ~11.8K loads in flight/SM.
// ---------------------------------------------------------------------------
__global__ __launch_bounds__(336) void k_means(const float* __restrict__ x) {
    const int c   = blockIdx.x;
    const int bs  = blockIdx.y;           // b*SS + s
    const int z   = blockIdx.z;           // strip group: strips z*7 .. z*7+6
    const int tid = threadIdx.x;
    const int q   = tid % 48;
    const int kh  = tid / 48;

    __shared__ float4 srow[7][KK][48];    // 37632 B  [g][kh][q]
    __shared__ float  scol[7][WW];        //  5376 B

    const float4* xim4 = (const float4*)(x + (size_t)(bs * CC + c) * HH * WW);
    const int s0 = z * 7;

    // 7 independent loads, front-batched
    float4 v[7];
    #pragma unroll
    for (int g = 0; g < 7; g++) {
        const int h = (s0 + g) * KK + kh;
        if (h < HH) v[g] = xim4[h * 48 + q];
        else        v[g] = make_float4(0.f, 0.f, 0.f, 0.f);
    }
    #pragma unroll
    for (int g = 0; g < 7; g++) srow[g][kh][q] = v[g];
    __syncthreads();

    // phase A: per strip, sum 7 rows -> 192 column sums. 336 tasks = block.
    {
        const int g = tid / 48, qq = tid % 48;
        float4 a = srow[g][0][qq];
        #pragma unroll
        for (int r = 1; r < KK; r++) {
            float4 b = srow[g][r][qq];
            a.x += b.x; a.y += b.y; a.z += b.z; a.w += b.w;
        }
        *(float4*)&scol[g][qq * 4] = a;
    }
    __syncthreads();

    // phase B: 7-col window sums (196 tasks)
    if (tid < 7 * NW) {
        const int g = tid / NW, nw = tid % NW;
        const int w0 = nw * KK;
        float ws = 0.f;
        #pragma unroll
        for (int i = 0; i < KK; i++) {
            const int w = w0 + i;
            if (w < WW) ws += scol[g][w];
        }
        g_buf[((size_t)(bs * CC + c) * NH + (s0 + g)) * NW + nw] = ws * (1.0f / (KK * KK));
    }
}

// ---------------------------------------------------------------------------
// Kernel 2: tiny MLP over C -> logits[b,s,nh,nw]
// grid (NH, SS, BB), block 448 = NW*HID
// ---------------------------------------------------------------------------
__global__ void k_mlp(const float* __restrict__ w1, const float* __restrict__ b1,
                      const float* __restrict__ w2, const float* __restrict__ b2,
                      const float* __restrict__ stat) {
    const int nh = blockIdx.x;
    const int s  = blockIdx.y;
    const int b  = blockIdx.z;
    const int tid = threadIdx.x;

    __shared__ float sg[CC * NW];
    __shared__ float sw1[HID * CC];
    __shared__ float sh[NW * HID];

    const size_t gbase = (size_t)(b * SS + s) * CC * NH * NW + (size_t)nh * NW;
    for (int i = tid; i < CC * NW; i += blockDim.x) {
        int c = i / NW, nw = i % NW;
        sg[i] = g_buf[gbase + (size_t)c * NH * NW + nw];
    }
    for (int i = tid; i < HID * CC; i += blockDim.x) sw1[i] = w1[i];
    __syncthreads();

    {
        const int nw = tid % NW;
        const int j  = tid / NW;
        float acc = b1[j];
        #pragma unroll 8
        for (int c = 0; c < CC; c++)
            acc = fmaf(sg[c * NW + nw], sw1[j * CC + c], acc);
        sh[nw * HID + j] = fmaxf(acc, 0.f);
    }
    __syncthreads();

    if (tid < NW) {
        float lg = b2[0] + stat[s];
        #pragma unroll
        for (int j = 0; j < HID; j++) lg = fmaf(sh[tid * HID + j], w2[j], lg);
        logits_buf[((size_t)(b * SS + s) * NH + nh) * NW + tid] = lg;
    }
}

// ---------------------------------------------------------------------------
// Kernel 3: softmax over S + weighted fuse, 2 channels per block.
// Block = 480 threads = 48 quads x 10 rows; each thread does exactly 7
// unconditional, independent float4 loads covering all 70 rows.
// grid (NH, CC/2, BB), dynamic smem ~53 KB -> 4 blocks/SM.
// ---------------------------------------------------------------------------
#define FUSE_SM (SS * KK * WW)           // 6720 floats per channel
#define FUSE_T  480

__global__ __launch_bounds__(FUSE_T) void k_fuse(const float* __restrict__ x,
                                                 float* __restrict__ out) {
    const int nh = blockIdx.x;
    const int c0 = blockIdx.y * 2;
    const int b  = blockIdx.z;
    const int t  = threadIdx.x;          // 0..479

    extern __shared__ float smem[];
    float* sm  = smem;                   // [2*SS*KK][WW], r = (ci*SS+s)*KK+kh
    float* swt = smem + 2 * FUSE_SM;     // [SS][NW]

    const int h0 = nh * KK;
    const float4* x4 = (const float4*)x;

    // 7 front-batched independent loads per thread (q fixed, row += 10)
    const int q  = t % 48;
    const int r0 = t / 48;               // 0..9
    float4 v[7];
    int rr[7];
    #pragma unroll
    for (int it = 0; it < KK; it++) {
        const int r  = r0 + it * 10;     // 0..69
        const int kh = r % KK;
        const int sc = r / KK;           // ci*SS + s
        const int s  = sc % SS;
        const int ci = sc / SS;
        const int h  = h0 + kh;
        rr[it] = r;
        if (h < HH)
            v[it] = x4[((size_t)((b * SS + s) * CC + c0 + ci) * HH + h) * 48 + q];
        else
            v[it] = make_float4(0.f, 0.f, 0.f, 0.f);
    }
    #pragma unroll
    for (int it = 0; it < KK; it++)
        *(float4*)&sm[rr[it] * WW + q * 4] = v[it];

    // Softmax over S (28 windows, shared by both channels)
    if (t < NW) {
        float lg[SS];
        float mx = -1e30f;
        #pragma unroll
        for (int s = 0; s < SS; s++) {
            lg[s] = logits_buf[((size_t)(b * SS + s) * NH + nh) * NW + t];
            mx = fmaxf(mx, lg[s]);
        }
        float sum = 0.f;
        #pragma unroll
        for (int s = 0; s < SS; s++) { lg[s] = expf(lg[s] - mx); sum += lg[s]; }
        const float inv = 1.f / sum;
        #pragma unroll
        for (int s = 0; s < SS; s++) swt[s * NW + t] = lg[s] * inv;
    }
    __syncthreads();

    // Compute + store: threads 0..383 -> (ci, output column)
    if (t < 2 * WW) {
        const int ci   = t / WW;
        const int col  = t % WW;
        const int kw   = col / NW;
        const int nw   = col % NW;
        const int wsrc = nw * KK + kw;
        const bool valid = (wsrc < WW);

        float wts[SS];
        #pragma unroll
        for (int s = 0; s < SS; s++) wts[s] = swt[s * NW + nw];

        const float* smc = sm + ci * SS * KK * WW;
        float* obase = out + (size_t)(b * CC + c0 + ci) * HH * WW;
        #pragma unroll
        for (int kh = 0; kh < KK; kh++) {
            const int y = kh * NH + nh;
            if (y < HH) {
                float vv = 0.f;
                if (valid) {
                    #pragma unroll
                    for (int s = 0; s < SS; s++)
                        vv = fmaf(wts[s], smc[(s * KK + kh) * WW + wsrc], vv);
                }
                obase[(size_t)y * WW + col] = vv;
            }
        }
    }
}

// ---------------------------------------------------------------------------
extern "C" void kernel_launch(void* const* d_in, const int* in_sizes, int n_in,
                              void* d_out, int out_size) {
    const float* x    = (const float*)d_in[0];
    const float* w1   = (const float*)d_in[1];
    const float* b1   = (const float*)d_in[2];
    const float* w2   = (const float*)d_in[3];
    const float* b2   = (const float*)d_in[4];
    const float* stat = (const float*)d_in[5];
    float* out = (float*)d_out;

    const int fuse_smem = (2 * FUSE_SM + SS * NW) * sizeof(float);  // ~53 KB
    cudaFuncSetAttribute(k_fuse, cudaFuncAttributeMaxDynamicSharedMemorySize, fuse_smem);

    k_means<<<dim3(CC, BB * SS, 4), 336>>>(x);
    k_mlp  <<<dim3(NH, SS, BB), NW * HID>>>(w1, b1, w2, b2, stat);
    k_fuse <<<dim3(NH, CC / 2, BB), FUSE_T, fuse_smem>>>(x, out);
}

// round 7
// speedup vs baseline: 8.6148x; 1.0978x over previous
#include <cuda_runtime.h>

#define BB 2
#define SS 5
#define CC 256
#define HH 192
#define WW 192
#define KK 7
#define NH 28
#define NW 28
#define HID 16

__device__ float g_buf[BB * SS * CC * NH * NW];       // 8.03 MB
__device__ float logits_buf[BB * SS * NH * NW];       // 31.4 KB

// ---------------------------------------------------------------------------
// Kernel 1: 7x7 window means, register-sum variant.
// Thread (g,q) = strip g (of 7 per block), float4-quad q: loads the SAME quad
// of all 7 rows of its strip (7 independent front-batched loads), sums in
// registers -> column sums, ONE barrier, then 7-col window sums.
// smem 5.4 KB -> 6 blocks/SM (2016 thr = cap), ~14.1K loads in flight/SM.
// grid (CC, BB*SS, 4), block 336.
// ---------------------------------------------------------------------------
__global__ __launch_bounds__(336) void k_means(const float* __restrict__ x) {
    const int c   = blockIdx.x;
    const int bs  = blockIdx.y;           // b*SS + s
    const int z   = blockIdx.z;           // strips z*7 .. z*7+6
    const int tid = threadIdx.x;
    const int g   = tid / 48;             // strip within group (0..6)
    const int q   = tid % 48;             // float4 quad (0..47)

    __shared__ float scol[7][WW];         // 5376 B

    const float4* xim4 = (const float4*)(x + (size_t)(bs * CC + c) * HH * WW);
    const int strip = z * 7 + g;
    const int h0 = strip * KK;

    // 7 independent loads, front-batched (no smem staging)
    float4 v[7];
    #pragma unroll
    for (int kh = 0; kh < KK; kh++) {
        const int h = h0 + kh;
        if (h < HH) v[kh] = xim4[h * 48 + q];
        else        v[kh] = make_float4(0.f, 0.f, 0.f, 0.f);
    }
    // register tree-sum of the 7 rows
    float4 a01, a23, a45, a;
    a01.x = v[0].x + v[1].x; a01.y = v[0].y + v[1].y; a01.z = v[0].z + v[1].z; a01.w = v[0].w + v[1].w;
    a23.x = v[2].x + v[3].x; a23.y = v[2].y + v[3].y; a23.z = v[2].z + v[3].z; a23.w = v[2].w + v[3].w;
    a45.x = v[4].x + v[5].x; a45.y = v[4].y + v[5].y; a45.z = v[4].z + v[5].z; a45.w = v[4].w + v[5].w;
    a.x = (a01.x + a23.x) + (a45.x + v[6].x);
    a.y = (a01.y + a23.y) + (a45.y + v[6].y);
    a.z = (a01.z + a23.z) + (a45.z + v[6].z);
    a.w = (a01.w + a23.w) + (a45.w + v[6].w);
    *(float4*)&scol[g][q * 4] = a;
    __syncthreads();

    // 7-col window sums (196 tasks)
    if (tid < 7 * NW) {
        const int gg = tid / NW, nw = tid % NW;
        const int w0 = nw * KK;
        float ws = 0.f;
        #pragma unroll
        for (int i = 0; i < KK; i++) {
            const int w = w0 + i;
            if (w < WW) ws += scol[gg][w];
        }
        g_buf[((size_t)(bs * CC + c) * NH + (z * 7 + gg)) * NW + nw] = ws * (1.0f / (KK * KK));
    }
}

// ---------------------------------------------------------------------------
// Kernel 2: tiny MLP over C -> logits[b,s,nh,nw]
// grid (NH, SS, BB), block 448 = NW*HID
// ---------------------------------------------------------------------------
__global__ void k_mlp(const float* __restrict__ w1, const float* __restrict__ b1,
                      const float* __restrict__ w2, const float* __restrict__ b2,
                      const float* __restrict__ stat) {
    const int nh = blockIdx.x;
    const int s  = blockIdx.y;
    const int b  = blockIdx.z;
    const int tid = threadIdx.x;

    __shared__ float sg[CC * NW];
    __shared__ float sw1[HID * CC];
    __shared__ float sh[NW * HID];

    const size_t gbase = (size_t)(b * SS + s) * CC * NH * NW + (size_t)nh * NW;
    for (int i = tid; i < CC * NW; i += blockDim.x) {
        int c = i / NW, nw = i % NW;
        sg[i] = g_buf[gbase + (size_t)c * NH * NW + nw];
    }
    for (int i = tid; i < HID * CC; i += blockDim.x) sw1[i] = w1[i];
    __syncthreads();

    {
        const int nw = tid % NW;
        const int j  = tid / NW;
        float acc = b1[j];
        #pragma unroll 8
        for (int c = 0; c < CC; c++)
            acc = fmaf(sg[c * NW + nw], sw1[j * CC + c], acc);
        sh[nw * HID + j] = fmaxf(acc, 0.f);
    }
    __syncthreads();

    if (tid < NW) {
        float lg = b2[0] + stat[s];
        #pragma unroll
        for (int j = 0; j < HID; j++) lg = fmaf(sh[tid * HID + j], w2[j], lg);
        logits_buf[((size_t)(b * SS + s) * NH + nh) * NW + tid] = lg;
    }
}

// ---------------------------------------------------------------------------
// Kernel 3: softmax over S + weighted fuse, 2 channels per block.
// Block = 480 threads = 48 quads x 10 rows; each thread does exactly 7
// unconditional, independent float4 loads covering all 70 rows.
// grid (NH, CC/2, BB), dynamic smem ~53 KB -> 4 blocks/SM.
// ---------------------------------------------------------------------------
#define FUSE_SM (SS * KK * WW)           // 6720 floats per channel
#define FUSE_T  480

__global__ __launch_bounds__(FUSE_T) void k_fuse(const float* __restrict__ x,
                                                 float* __restrict__ out) {
    const int nh = blockIdx.x;
    const int c0 = blockIdx.y * 2;
    const int b  = blockIdx.z;
    const int t  = threadIdx.x;          // 0..479

    extern __shared__ float smem[];
    float* sm  = smem;                   // [2*SS*KK][WW], r = (ci*SS+s)*KK+kh
    float* swt = smem + 2 * FUSE_SM;     // [SS][NW]

    const int h0 = nh * KK;
    const float4* x4 = (const float4*)x;

    // 7 front-batched independent loads per thread (q fixed, row += 10)
    const int q  = t % 48;
    const int r0 = t / 48;               // 0..9
    float4 v[7];
    int rr[7];
    #pragma unroll
    for (int it = 0; it < KK; it++) {
        const int r  = r0 + it * 10;     // 0..69
        const int kh = r % KK;
        const int sc = r / KK;           // ci*SS + s
        const int s  = sc % SS;
        const int ci = sc / SS;
        const int h  = h0 + kh;
        rr[it] = r;
        if (h < HH)
            v[it] = x4[((size_t)((b * SS + s) * CC + c0 + ci) * HH + h) * 48 + q];
        else
            v[it] = make_float4(0.f, 0.f, 0.f, 0.f);
    }
    #pragma unroll
    for (int it = 0; it < KK; it++)
        *(float4*)&sm[rr[it] * WW + q * 4] = v[it];

    // Softmax over S (28 windows, shared by both channels)
    if (t < NW) {
        float lg[SS];
        float mx = -1e30f;
        #pragma unroll
        for (int s = 0; s < SS; s++) {
            lg[s] = logits_buf[((size_t)(b * SS + s) * NH + nh) * NW + t];
            mx = fmaxf(mx, lg[s]);
        }
        float sum = 0.f;
        #pragma unroll
        for (int s = 0; s < SS; s++) { lg[s] = expf(lg[s] - mx); sum += lg[s]; }
        const float inv = 1.f / sum;
        #pragma unroll
        for (int s = 0; s < SS; s++) swt[s * NW + t] = lg[s] * inv;
    }
    __syncthreads();

    // Compute + store: threads 0..383 -> (ci, output column)
    if (t < 2 * WW) {
        const int ci   = t / WW;
        const int col  = t % WW;
        const int kw   = col / NW;
        const int nw   = col % NW;
        const int wsrc = nw * KK + kw;
        const bool valid = (wsrc < WW);

        float wts[SS];
        #pragma unroll
        for (int s = 0; s < SS; s++) wts[s] = swt[s * NW + nw];

        const float* smc = sm + ci * SS * KK * WW;
        float* obase = out + (size_t)(b * CC + c0 + ci) * HH * WW;
        #pragma unroll
        for (int kh = 0; kh < KK; kh++) {
            const int y = kh * NH + nh;
            if (y < HH) {
                float vv = 0.f;
                if (valid) {
                    #pragma unroll
                    for (int s = 0; s < SS; s++)
                        vv = fmaf(wts[s], smc[(s * KK + kh) * WW + wsrc], vv);
                }
                obase[(size_t)y * WW + col] = vv;
            }
        }
    }
}

// ---------------------------------------------------------------------------
extern "C" void kernel_launch(void* const* d_in, const int* in_sizes, int n_in,
                              void* d_out, int out_size) {
    const float* x    = (const float*)d_in[0];
    const float* w1   = (const float*)d_in[1];
    const float* b1   = (const float*)d_in[2];
    const float* w2   = (const float*)d_in[3];
    const float* b2   = (const float*)d_in[4];
    const float* stat = (const float*)d_in[5];
    float* out = (float*)d_out;

    const int fuse_smem = (2 * FUSE_SM + SS * NW) * sizeof(float);  // ~53 KB
    cudaFuncSetAttribute(k_fuse, cudaFuncAttributeMaxDynamicSharedMemorySize, fuse_smem);

    k_means<<<dim3(CC, BB * SS, 4), 336>>>(x);
    k_mlp  <<<dim3(NH, SS, BB), NW * HID>>>(w1, b1, w2, b2, stat);
    k_fuse <<<dim3(NH, CC / 2, BB), FUSE_T, fuse_smem>>>(x, out);
}

// round 8
// speedup vs baseline: 8.6717x; 1.0066x over previous
#include <cuda_runtime.h>

#define BB 2
#define SS 5
#define CC 256
#define HH 192
#define WW 192
#define KK 7
#define NH 28
#define NW 28
#define HID 16

__device__ float g_buf[BB * SS * CC * NH * NW];       // 8.03 MB
__device__ float logits_buf[BB * SS * NH * NW];       // 31.4 KB

// ---------------------------------------------------------------------------
// Kernel 1: 7x7 window means, register-sum variant (validated R7: 81% DRAM).
// Thread (g,q): 7 front-batched float4 loads of one strip at quad q, register
// tree-sum, ONE barrier, 7-col window sums. grid (CC, BB*SS, 4), block 336.
// ---------------------------------------------------------------------------
__global__ __launch_bounds__(336) void k_means(const float* __restrict__ x) {
    const int c   = blockIdx.x;
    const int bs  = blockIdx.y;           // b*SS + s
    const int z   = blockIdx.z;           // strips z*7 .. z*7+6
    const int tid = threadIdx.x;
    const int g   = tid / 48;             // strip within group (0..6)
    const int q   = tid % 48;             // float4 quad (0..47)

    __shared__ float scol[7][WW];         // 5376 B

    const float4* xim4 = (const float4*)(x + (size_t)(bs * CC + c) * HH * WW);
    const int strip = z * 7 + g;
    const int h0 = strip * KK;

    float4 v[7];
    #pragma unroll
    for (int kh = 0; kh < KK; kh++) {
        const int h = h0 + kh;
        if (h < HH) v[kh] = xim4[h * 48 + q];
        else        v[kh] = make_float4(0.f, 0.f, 0.f, 0.f);
    }
    float4 a01, a23, a45, a;
    a01.x = v[0].x + v[1].x; a01.y = v[0].y + v[1].y; a01.z = v[0].z + v[1].z; a01.w = v[0].w + v[1].w;
    a23.x = v[2].x + v[3].x; a23.y = v[2].y + v[3].y; a23.z = v[2].z + v[3].z; a23.w = v[2].w + v[3].w;
    a45.x = v[4].x + v[5].x; a45.y = v[4].y + v[5].y; a45.z = v[4].z + v[5].z; a45.w = v[4].w + v[5].w;
    a.x = (a01.x + a23.x) + (a45.x + v[6].x);
    a.y = (a01.y + a23.y) + (a45.y + v[6].y);
    a.z = (a01.z + a23.z) + (a45.z + v[6].z);
    a.w = (a01.w + a23.w) + (a45.w + v[6].w);
    *(float4*)&scol[g][q * 4] = a;
    __syncthreads();

    if (tid < 7 * NW) {
        const int gg = tid / NW, nw = tid % NW;
        const int w0 = nw * KK;
        float ws = 0.f;
        #pragma unroll
        for (int i = 0; i < KK; i++) {
            const int w = w0 + i;
            if (w < WW) ws += scol[gg][w];
        }
        g_buf[((size_t)(bs * CC + c) * NH + (z * 7 + gg)) * NW + nw] = ws * (1.0f / (KK * KK));
    }
}

// ---------------------------------------------------------------------------
// Kernel 2: tiny MLP over C -> logits[b,s,nh,nw]
// grid (NH, SS, BB), block 448 = NW*HID
// ---------------------------------------------------------------------------
__global__ void k_mlp(const float* __restrict__ w1, const float* __restrict__ b1,
                      const float* __restrict__ w2, const float* __restrict__ b2,
                      const float* __restrict__ stat) {
    const int nh = blockIdx.x;
    const int s  = blockIdx.y;
    const int b  = blockIdx.z;
    const int tid = threadIdx.x;

    __shared__ float sg[CC * NW];
    __shared__ float sw1[HID * CC];
    __shared__ float sh[NW * HID];

    const size_t gbase = (size_t)(b * SS + s) * CC * NH * NW + (size_t)nh * NW;
    for (int i = tid; i < CC * NW; i += blockDim.x) {
        int c = i / NW, nw = i % NW;
        sg[i] = g_buf[gbase + (size_t)c * NH * NW + nw];
    }
    for (int i = tid; i < HID * CC; i += blockDim.x) sw1[i] = w1[i];
    __syncthreads();

    {
        const int nw = tid % NW;
        const int j  = tid / NW;
        float acc = b1[j];
        #pragma unroll 8
        for (int c = 0; c < CC; c++)
            acc = fmaf(sg[c * NW + nw], sw1[j * CC + c], acc);
        sh[nw * HID + j] = fmaxf(acc, 0.f);
    }
    __syncthreads();

    if (tid < NW) {
        float lg = b2[0] + stat[s];
        #pragma unroll
        for (int j = 0; j < HID; j++) lg = fmaf(sh[tid * HID + j], w2[j], lg);
        logits_buf[((size_t)(b * SS + s) * NH + nh) * NW + tid] = lg;
    }
}

// ---------------------------------------------------------------------------
// Kernel 3: softmax over S + weighted fuse, ONE channel per block.
// Block = 240 threads = 48 quads x 5 row-groups; each thread does exactly 7
// front-batched independent float4 loads covering all 35 rows (5s x 7kh).
// smem 27.5 KB -> 8 blocks/SM: load fronts of 7 sibling blocks cover each
// block's compute/store phase. grid (NH, CC, BB).
// ---------------------------------------------------------------------------
#define FUSE_T 240

__global__ __launch_bounds__(FUSE_T) void k_fuse(const float* __restrict__ x,
                                                 float* __restrict__ out) {
    const int nh = blockIdx.x;
    const int c  = blockIdx.y;
    const int b  = blockIdx.z;
    const int t  = threadIdx.x;          // 0..239

    __shared__ float sm[SS * KK * WW];   // 26880 B : rows r = s*KK + kh
    __shared__ float swt[SS * NW];       //   560 B

    const int h0 = nh * KK;
    const float4* x4 = (const float4*)x;

    // 7 front-batched independent loads per thread (q fixed, row += 5)
    const int q  = t % 48;
    const int r0 = t / 48;               // 0..4
    float4 v[7];
    int rr[7];
    #pragma unroll
    for (int it = 0; it < KK; it++) {
        const int r  = r0 + it * 5;      // 0..34
        const int kh = r % KK;
        const int s  = r / KK;
        const int h  = h0 + kh;
        rr[it] = r;
        if (h < HH)
            v[it] = x4[((size_t)((b * SS + s) * CC + c) * HH + h) * 48 + q];
        else
            v[it] = make_float4(0.f, 0.f, 0.f, 0.f);
    }
    #pragma unroll
    for (int it = 0; it < KK; it++)
        *(float4*)&sm[rr[it] * WW + q * 4] = v[it];

    // Softmax over S (28 windows)
    if (t < NW) {
        float lg[SS];
        float mx = -1e30f;
        #pragma unroll
        for (int s = 0; s < SS; s++) {
            lg[s] = logits_buf[((size_t)(b * SS + s) * NH + nh) * NW + t];
            mx = fmaxf(mx, lg[s]);
        }
        float sum = 0.f;
        #pragma unroll
        for (int s = 0; s < SS; s++) { lg[s] = expf(lg[s] - mx); sum += lg[s]; }
        const float inv = 1.f / sum;
        #pragma unroll
        for (int s = 0; s < SS; s++) swt[s * NW + t] = lg[s] * inv;
    }
    __syncthreads();

    // Compute + store: threads 0..191 -> output column
    if (t < WW) {
        const int kw   = t / NW;
        const int nw   = t % NW;
        const int wsrc = nw * KK + kw;
        const bool valid = (wsrc < WW);

        float wts[SS];
        #pragma unroll
        for (int s = 0; s < SS; s++) wts[s] = swt[s * NW + nw];

        float* obase = out + (size_t)(b * CC + c) * HH * WW;
        #pragma unroll
        for (int kh = 0; kh < KK; kh++) {
            const int y = kh * NH + nh;
            if (y < HH) {
                float vv = 0.f;
                if (valid) {
                    #pragma unroll
                    for (int s = 0; s < SS; s++)
                        vv = fmaf(wts[s], sm[(s * KK + kh) * WW + wsrc], vv);
                }
                obase[(size_t)y * WW + t] = vv;
            }
        }
    }
}

// ---------------------------------------------------------------------------
extern "C" void kernel_launch(void* const* d_in, const int* in_sizes, int n_in,
                              void* d_out, int out_size) {
    const float* x    = (const float*)d_in[0];
    const float* w1   = (const float*)d_in[1];
    const float* b1   = (const float*)d_in[2];
    const float* w2   = (const float*)d_in[3];
    const float* b2   = (const float*)d_in[4];
    const float* stat = (const float*)d_in[5];
    float* out = (float*)d_out;

    k_means<<<dim3(CC, BB * SS, 4), 336>>>(x);
    k_mlp  <<<dim3(NH, SS, BB), NW * HID>>>(w1, b1, w2, b2, stat);
    k_fuse <<<dim3(NH, CC, BB), FUSE_T>>>(x, out);
}

// round 9
// speedup vs baseline: 8.9947x; 1.0372x over previous
#include <cuda_runtime.h>
#include <cstdint>

#define BB 2
#define SS 5
#define CC 256
#define HH 192
#define WW 192
#define KK 7
#define NH 28
#define NW 28
#define HID 16

__device__ float g_buf[BB * SS * CC * NH * NW];       // 8.03 MB
__device__ float logits_buf[BB * SS * NH * NW];       // 31.4 KB

// ---------------------------------------------------------------------------
// Kernel 1: 7x7 window means, register-sum variant (validated R7/R8 ~80% DRAM)
// ---------------------------------------------------------------------------
__global__ __launch_bounds__(336) void k_means(const float* __restrict__ x) {
    const int c   = blockIdx.x;
    const int bs  = blockIdx.y;
    const int z   = blockIdx.z;
    const int tid = threadIdx.x;
    const int g   = tid / 48;
    const int q   = tid % 48;

    __shared__ float scol[7][WW];

    const float4* xim4 = (const float4*)(x + (size_t)(bs * CC + c) * HH * WW);
    const int strip = z * 7 + g;
    const int h0 = strip * KK;

    float4 v[7];
    #pragma unroll
    for (int kh = 0; kh < KK; kh++) {
        const int h = h0 + kh;
        if (h < HH) v[kh] = xim4[h * 48 + q];
        else        v[kh] = make_float4(0.f, 0.f, 0.f, 0.f);
    }
    float4 a01, a23, a45, a;
    a01.x = v[0].x + v[1].x; a01.y = v[0].y + v[1].y; a01.z = v[0].z + v[1].z; a01.w = v[0].w + v[1].w;
    a23.x = v[2].x + v[3].x; a23.y = v[2].y + v[3].y; a23.z = v[2].z + v[3].z; a23.w = v[2].w + v[3].w;
    a45.x = v[4].x + v[5].x; a45.y = v[4].y + v[5].y; a45.z = v[4].z + v[5].z; a45.w = v[4].w + v[5].w;
    a.x = (a01.x + a23.x) + (a45.x + v[6].x);
    a.y = (a01.y + a23.y) + (a45.y + v[6].y);
    a.z = (a01.z + a23.z) + (a45.z + v[6].z);
    a.w = (a01.w + a23.w) + (a45.w + v[6].w);
    *(float4*)&scol[g][q * 4] = a;
    __syncthreads();

    if (tid < 7 * NW) {
        const int gg = tid / NW, nw = tid % NW;
        const int w0 = nw * KK;
        float ws = 0.f;
        #pragma unroll
        for (int i = 0; i < KK; i++) {
            const int w = w0 + i;
            if (w < WW) ws += scol[gg][w];
        }
        g_buf[((size_t)(bs * CC + c) * NH + (z * 7 + gg)) * NW + nw] = ws * (1.0f / (KK * KK));
    }
}

// ---------------------------------------------------------------------------
// Kernel 2: tiny MLP over C -> logits (unchanged)
// ---------------------------------------------------------------------------
__global__ void k_mlp(const float* __restrict__ w1, const float* __restrict__ b1,
                      const float* __restrict__ w2, const float* __restrict__ b2,
                      const float* __restrict__ stat) {
    const int nh = blockIdx.x;
    const int s  = blockIdx.y;
    const int b  = blockIdx.z;
    const int tid = threadIdx.x;

    __shared__ float sg[CC * NW];
    __shared__ float sw1[HID * CC];
    __shared__ float sh[NW * HID];

    const size_t gbase = (size_t)(b * SS + s) * CC * NH * NW + (size_t)nh * NW;
    for (int i = tid; i < CC * NW; i += blockDim.x) {
        int c = i / NW, nw = i % NW;
        sg[i] = g_buf[gbase + (size_t)c * NH * NW + nw];
    }
    for (int i = tid; i < HID * CC; i += blockDim.x) sw1[i] = w1[i];
    __syncthreads();

    {
        const int nw = tid % NW;
        const int j  = tid / NW;
        float acc = b1[j];
        #pragma unroll 8
        for (int c = 0; c < CC; c++)
            acc = fmaf(sg[c * NW + nw], sw1[j * CC + c], acc);
        sh[nw * HID + j] = fmaxf(acc, 0.f);
    }
    __syncthreads();

    if (tid < NW) {
        float lg = b2[0] + stat[s];
        #pragma unroll
        for (int j = 0; j < HID; j++) lg = fmaf(sh[tid * HID + j], w2[j], lg);
        logits_buf[((size_t)(b * SS + s) * NH + nh) * NW + tid] = lg;
    }
}

// ---------------------------------------------------------------------------
// Kernel 3: TMA double-buffered fuse. Block handles CPB channels of one strip
// sequentially; cp.async.bulk prefetches channel ch+2 into the spare buffer
// while threads compute+store channel ch -> load stream decoupled from warp
// phases. Softmax computed once per block. grid (NH, CC/CPB, BB), block 256,
// dynamic smem 54.3 KB -> 4 blocks/SM.
// ---------------------------------------------------------------------------
#define CPB 8
#define FT  256
#define CH_FLOATS (SS * KK * WW)          // 6720 floats per channel buffer

__device__ __forceinline__ uint32_t smem_u32(const void* p) {
    uint32_t a;
    asm("{ .reg .u64 t; cvta.to.shared.u64 t, %1; cvt.u32.u64 %0, t; }"
        : "=r"(a) : "l"(p));
    return a;
}

__global__ __launch_bounds__(FT) void k_fuse(const float* __restrict__ x,
                                             float* __restrict__ out) {
    const int nh = blockIdx.x;
    const int cb = blockIdx.y;            // channel group
    const int b  = blockIdx.z;
    const int t  = threadIdx.x;

    extern __shared__ float smem[];
    float* buf = smem;                    // [2][CH_FLOATS]
    float* swt = smem + 2 * CH_FLOATS;    // [SS*NW]
    __shared__ __align__(8) unsigned long long fullbar[2];

    const uint32_t bar0 = smem_u32(&fullbar[0]);
    const uint32_t bar1 = smem_u32(&fullbar[1]);
    const uint32_t bufa = smem_u32(buf);

    const int h0    = nh * KK;
    const int vrows = (HH - h0 < KK) ? (HH - h0) : KK;   // 7, or 3 at nh=27
    const uint32_t slice_bytes = (uint32_t)vrows * WW * 4;

    // init barriers + zero pad rows (only touched when vrows < KK; TMA never
    // writes them, compute reads them as zero)
    if (t == 0) {
        asm volatile("mbarrier.init.shared.b64 [%0], %1;" :: "r"(bar0), "r"(1u));
        asm volatile("mbarrier.init.shared.b64 [%0], %1;" :: "r"(bar1), "r"(1u));
        asm volatile("fence.proxy.async.shared::cta;" ::: "memory");
    }
    if (vrows < KK) {
        // zero rows vrows..6 of each slice, both stages
        const int padrows = KK - vrows;
        const int total = 2 * SS * padrows * WW;
        for (int i = t; i < total; i += FT) {
            const int w  = i % WW;
            const int r  = i / WW;               // (p*SS + s)*padrows + pr
            const int pr = r % padrows;
            const int ps = r / padrows;          // p*SS + s
            buf[ps * KK * WW + (vrows + pr) * WW + w] = 0.f;
        }
    }

    // producer: issue channel ch into stage ch&1
    auto issue = [&](int ch) {
        const int c = cb * CPB + ch;
        const int p = ch & 1;
        const uint32_t mbar = p ? bar1 : bar0;
        asm volatile("mbarrier.arrive.expect_tx.shared.b64 _, [%0], %1;"
                     :: "r"(mbar), "r"(slice_bytes * SS) : "memory");
        #pragma unroll
        for (int s = 0; s < SS; s++) {
            const float* src = x + ((size_t)((b * SS + s) * CC + c) * HH + h0) * WW;
            const uint32_t dst = bufa + (uint32_t)(p * CH_FLOATS + s * KK * WW) * 4;
            asm volatile(
                "cp.async.bulk.shared::cta.global.mbarrier::complete_tx::bytes "
                "[%0], [%1], %2, [%3];"
                :: "r"(dst), "l"(src), "r"(slice_bytes), "r"(mbar) : "memory");
        }
    };

    if (t == 0) { issue(0); issue(1); }

    // softmax over S (28 windows, shared by all CPB channels)
    if (t < NW) {
        float lg[SS];
        float mx = -1e30f;
        #pragma unroll
        for (int s = 0; s < SS; s++) {
            lg[s] = logits_buf[((size_t)(b * SS + s) * NH + nh) * NW + t];
            mx = fmaxf(mx, lg[s]);
        }
        float sum = 0.f;
        #pragma unroll
        for (int s = 0; s < SS; s++) { lg[s] = expf(lg[s] - mx); sum += lg[s]; }
        const float inv = 1.f / sum;
        #pragma unroll
        for (int s = 0; s < SS; s++) swt[s * NW + t] = lg[s] * inv;
    }
    __syncthreads();   // barriers init'd + swt visible to all

    // per-thread store-phase constants
    const int kw   = t / NW;              // valid for t < 192
    const int nw   = t % NW;
    const int wsrc = nw * KK + kw;
    const bool valid = (t < WW) && (wsrc < WW);
    float wts[SS];
    #pragma unroll
    for (int s = 0; s < SS; s++) wts[s] = swt[s * NW + (t % NW)];

    for (int ch = 0; ch < CPB; ch++) {
        const int p  = ch & 1;
        const uint32_t mbar = p ? bar1 : bar0;
        const uint32_t ph = (ch >> 1) & 1;

        // all threads wait for stage-p data
        asm volatile(
            "{\n\t.reg .pred P;\n\t"
            "WL_%=:\n\t"
            "mbarrier.try_wait.parity.shared.b64 P, [%0], %1;\n\t"
            "@P bra.uni WD_%=;\n\t"
            "bra.uni WL_%=;\n\t"
            "WD_%=:\n\t}"
            :: "r"(mbar), "r"(ph) : "memory");

        if (t < WW) {
            const float* smc = buf + p * CH_FLOATS;
            const int c = cb * CPB + ch;
            float* obase = out + (size_t)(b * CC + c) * HH * WW;
            #pragma unroll
            for (int kh = 0; kh < KK; kh++) {
                const int y = kh * NH + nh;
                if (y < HH) {
                    float vv = 0.f;
                    if (valid) {
                        #pragma unroll
                        for (int s = 0; s < SS; s++)
                            vv = fmaf(wts[s], smc[(s * KK + kh) * WW + wsrc], vv);
                    }
                    obase[(size_t)y * WW + t] = vv;
                }
            }
        }
        __syncthreads();                  // buffer p fully consumed
        if (t == 0 && ch + 2 < CPB) issue(ch + 2);
    }
}

// ---------------------------------------------------------------------------
extern "C" void kernel_launch(void* const* d_in, const int* in_sizes, int n_in,
                              void* d_out, int out_size) {
    const float* x    = (const float*)d_in[0];
    const float* w1   = (const float*)d_in[1];
    const float* b1   = (const float*)d_in[2];
    const float* w2   = (const float*)d_in[3];
    const float* b2   = (const float*)d_in[4];
    const float* stat = (const float*)d_in[5];
    float* out = (float*)d_out;

    const int fuse_smem = (2 * CH_FLOATS + SS * NW) * sizeof(float);  // 54320 B
    cudaFuncSetAttribute(k_fuse, cudaFuncAttributeMaxDynamicSharedMemorySize, fuse_smem);

    k_means<<<dim3(CC, BB * SS, 4), 336>>>(x);
    k_mlp  <<<dim3(NH, SS, BB), NW * HID>>>(w1, b1, w2, b2, stat);
    k_fuse <<<dim3(NH, CC / CPB, BB), FT, fuse_smem>>>(x, out);
}